// round 8
// baseline (speedup 1.0000x reference)
#include <cuda_runtime.h>
#include <cuda_bf16.h>
#include <math.h>

#define PAD 8192
#define B 32
#define K 32
#define L 128
#define H1 512
#define H2 64
#define BAGS 4
#define NT 256
#define XS 516          // float stride per poi bag (2064B, 16B multiple)
#define HS 68           // multiple of 4 -> float4-safe
#define NQBLK 32
#define NPBLK 256
#define NBLK (NQBLK + NPBLK)

__device__ float g_qsw[B * L];
__device__ float g_ts[B * K];
__device__ int   g_qflag[B];
__device__ int   g_bcnt[B];

__device__ __forceinline__ float prelu(float x, float a) {
    return x >= 0.f ? x : a * x;
}

__global__ __launch_bounds__(NT, 4)
void urban_kernel(const int* __restrict__ qbf,
                  const int* __restrict__ pbf,
                  const float* __restrict__ qloc,
                  const float* __restrict__ ploc,
                  const float* __restrict__ cw,
                  const float* __restrict__ qW1, const float* __restrict__ qb1,
                  const float* __restrict__ qW2, const float* __restrict__ qb2,
                  const float* __restrict__ pW1, const float* __restrict__ pb1,
                  const float* __restrict__ pW2, const float* __restrict__ pb2,
                  const float* __restrict__ qew, const float* __restrict__ pew,
                  const float* __restrict__ qa0p, const float* __restrict__ qa1p,
                  const float* __restrict__ qa2p, const float* __restrict__ pa0p,
                  const float* __restrict__ pa1p, const float* __restrict__ pa2p,
                  const float* __restrict__ indap,
                  const float* __restrict__ ap, const float* __restrict__ bp,
                  const float* __restrict__ cp, const float* __restrict__ dp,
                  float* __restrict__ out) {
    __shared__ int      qidx[L];
    __shared__ int      pidx[BAGS * L];
    __shared__ unsigned bitmap[BAGS * 256];
    __shared__ __align__(16) float x[BAGS * XS];
    __shared__ __align__(16) float qx[H1];
    __shared__ float    mp[4 * 256];
    __shared__ float    qpart[4 * 64];
    __shared__ __align__(16) float h1s[BAGS * HS];
    __shared__ __align__(16) float phs[BAGS * HS];
    __shared__ float    qh1[H2];
    __shared__ __align__(16) float qh[H2];
    __shared__ float    qsw[L];
    __shared__ float    wpart[2][8];
    __shared__ int      s_is_last;

    const int tid = threadIdx.x;
    const int bid = blockIdx.x;

    if (bid < NQBLK) {
        // ================= QUERY BLOCK: one b =================
        const int b = bid;
        const float a0 = *qa0p, a1 = *qa1p, a2 = *qa2p;
        const float ind_a = *indap;

        if (tid < L) qidx[tid] = qbf[(size_t)b * L + tid];
        __syncthreads();

        // gather: two columns per thread, count fused
        {
            float acc0 = 0.f, acc1 = 0.f;
            int cnt = 0;
#pragma unroll 4
            for (int l = 0; l < L; l++) {
                int v = qidx[l];
                bool ok = (v != PAD);
                cnt += ok;
                float m = ok ? 1.f : 0.f;
                const float* row = cw + (size_t)v * H1;
                acc0 = fmaf(m, __ldg(row + tid), acc0);
                acc1 = fmaf(m, __ldg(row + tid + 256), acc1);
            }
            float inv = cnt > 0 ? 1.f / (float)cnt : 0.f;
            qx[tid]       = prelu(acc0 * inv, a0);
            qx[tid + 256] = prelu(acc1 * inv, a0);
        }
        __syncthreads();

        // MLP1: thread = (j, dp), 4 d-parts of 128
        {
            int j = tid & 63, dpp = tid >> 6;
            const float* w = qW1 + (size_t)(dpp * 128) * H2 + j;
            const float4* xq4 = (const float4*)(&qx[dpp * 128]);
            float acc = 0.f;
#pragma unroll 8
            for (int d4 = 0; d4 < 32; d4++) {
                float4 xv = xq4[d4];
                acc = fmaf(xv.x, __ldg(w + (d4 * 4 + 0) * H2), acc);
                acc = fmaf(xv.y, __ldg(w + (d4 * 4 + 1) * H2), acc);
                acc = fmaf(xv.z, __ldg(w + (d4 * 4 + 2) * H2), acc);
                acc = fmaf(xv.w, __ldg(w + (d4 * 4 + 3) * H2), acc);
            }
            qpart[dpp * 64 + j] = acc;
        }
        __syncthreads();
        if (tid < H2) {
            float acc = qb1[tid] + qpart[tid] + qpart[64 + tid] +
                        qpart[128 + tid] + qpart[192 + tid];
            qh1[tid] = prelu(acc, a1);
        }
        __syncthreads();
        {
            int j = tid & 63, dpp = tid >> 6;
            const float* w = qW2 + (size_t)(dpp * 16) * H2 + j;
            float acc = 0.f;
#pragma unroll
            for (int d = 0; d < 16; d++)
                acc = fmaf(qh1[dpp * 16 + d], __ldg(w + d * H2), acc);
            qpart[dpp * 64 + j] = acc;
        }
        __syncthreads();
        if (tid < H2) {
            float acc = qb2[tid] + qpart[tid] + qpart[64 + tid] +
                        qpart[128 + tid] + qpart[192 + tid];
            qh[tid] = prelu(acc, a2);
        }
        __syncthreads();

        if (tid < L) {
            int v = qidx[tid];
            float s = 0.f;
            if (v != PAD) {
                const float4* qr4 = (const float4*)(qew + (size_t)v * H2);
                const float4* qh4 = (const float4*)qh;
                float qd = 0.f;
#pragma unroll
                for (int h = 0; h < 16; h++) {
                    float4 r = __ldg(qr4 + h), q = qh4[h];
                    qd += r.x * q.x + r.y * q.y + r.z * q.z + r.w * q.w;
                }
                s = prelu(qd, ind_a) + 1.f;
            }
            __stcg(&g_qsw[b * L + tid], s);
        }
        __syncthreads();
        if (tid == 0) {
            __threadfence();
            atomicExch(&g_qflag[b], 1);
        }
    } else {
        // ================= POI BLOCK: 4 (b,k) pairs, same b =================
        const int pair0 = (bid - NQBLK) * BAGS;
        const int bb = pair0 >> 5;
        const float a0 = *pa0p, a1 = *pa1p, a2 = *pa2p;
        const float ind_a = *indap;

        for (int t = tid; t < BAGS * L; t += NT)
            pidx[t] = pbf[(size_t)pair0 * L + t];
        if (tid < L) qidx[tid] = qbf[(size_t)bb * L + tid];
        for (int t = tid; t < BAGS * 256; t += NT)
            bitmap[t] = 0u;
        __syncthreads();

        // ---- gather: 4 bags x 64 threads, 2 float4 columns per thread ----
        {
            const int g = tid >> 6, slot = tid & 63;
            const int* ip = &pidx[g * L];
            const float4* cw4 = (const float4*)cw;
            float4 acc0 = make_float4(0.f, 0.f, 0.f, 0.f);
            float4 acc1 = make_float4(0.f, 0.f, 0.f, 0.f);
            int cnt = 0;
#pragma unroll 4
            for (int l = 0; l < L; l++) {
                int v = ip[l];
                bool ok = (v != PAD);
                cnt += ok;
                float m = ok ? 1.f : 0.f;
                const float4* row = cw4 + (size_t)v * 128;
                float4 r0 = __ldg(row + slot);
                float4 r1 = __ldg(row + 64 + slot);
                acc0.x = fmaf(m, r0.x, acc0.x); acc0.y = fmaf(m, r0.y, acc0.y);
                acc0.z = fmaf(m, r0.z, acc0.z); acc0.w = fmaf(m, r0.w, acc0.w);
                acc1.x = fmaf(m, r1.x, acc1.x); acc1.y = fmaf(m, r1.y, acc1.y);
                acc1.z = fmaf(m, r1.z, acc1.z); acc1.w = fmaf(m, r1.w, acc1.w);
            }
            float inv = cnt > 0 ? 1.f / (float)cnt : 0.f;
            float4 o0, o1;
            o0.x = prelu(acc0.x * inv, a0); o0.y = prelu(acc0.y * inv, a0);
            o0.z = prelu(acc0.z * inv, a0); o0.w = prelu(acc0.w * inv, a0);
            o1.x = prelu(acc1.x * inv, a0); o1.y = prelu(acc1.y * inv, a0);
            o1.z = prelu(acc1.z * inv, a0); o1.w = prelu(acc1.w * inv, a0);
            *(float4*)(&x[g * XS] + slot * 4)        = o0;
            *(float4*)(&x[g * XS] + (64 + slot) * 4) = o1;
        }
        __syncthreads();

        // ---- bitmap build (same phase as MLP1) ----
        for (int t = tid; t < BAGS * L; t += NT) {
            int v = pidx[t];
            if (v != PAD)
                atomicOr(&bitmap[(t >> 7) * 256 + (v >> 5)], 1u << (v & 31));
        }
        // ---- MLP1: one W1 load feeds 4 bag-accumulators; float4 LDS ----
        {
            int j = tid & 63, dpp = tid >> 6;   // 4 d-parts of 128
            const float* w = pW1 + (size_t)(dpp * 128) * H2 + j;
            const float4* x0 = (const float4*)(&x[0 * XS + dpp * 128]);
            const float4* x1 = (const float4*)(&x[1 * XS + dpp * 128]);
            const float4* x2 = (const float4*)(&x[2 * XS + dpp * 128]);
            const float4* x3 = (const float4*)(&x[3 * XS + dpp * 128]);
            float f0 = 0.f, f1 = 0.f, f2 = 0.f, f3 = 0.f;
#pragma unroll 4
            for (int d4 = 0; d4 < 32; d4++) {
                float4 a = x0[d4], bv = x1[d4], cv = x2[d4], dv = x3[d4];
#pragma unroll
                for (int u = 0; u < 4; u++) {
                    float wv = __ldg(w + (d4 * 4 + u) * H2);
                    float av = (&a.x)[u], bvv = (&bv.x)[u];
                    float cvv = (&cv.x)[u], dvv = (&dv.x)[u];
                    f0 = fmaf(av, wv, f0);
                    f1 = fmaf(bvv, wv, f1);
                    f2 = fmaf(cvv, wv, f2);
                    f3 = fmaf(dvv, wv, f3);
                }
            }
            mp[dpp * 256 + j]       = f0;
            mp[dpp * 256 + 64 + j]  = f1;
            mp[dpp * 256 + 128 + j] = f2;
            mp[dpp * 256 + 192 + j] = f3;
        }
        __syncthreads();
        {
            int j = tid & 63, g = tid >> 6;
            float acc = pb1[j] + mp[g * 64 + j] + mp[256 + g * 64 + j] +
                        mp[512 + g * 64 + j] + mp[768 + g * 64 + j];
            h1s[g * HS + j] = prelu(acc, a1);
        }
        __syncthreads();
        // ---- MLP2: one W2 load feeds 4 bags; float4 LDS ----
        {
            int j = tid & 63, dpp = tid >> 6;   // 4 d-parts of 16
            const float* w = pW2 + (size_t)(dpp * 16) * H2 + j;
            const float4* h0 = (const float4*)(&h1s[0 * HS + dpp * 16]);
            const float4* h1 = (const float4*)(&h1s[1 * HS + dpp * 16]);
            const float4* h2 = (const float4*)(&h1s[2 * HS + dpp * 16]);
            const float4* h3 = (const float4*)(&h1s[3 * HS + dpp * 16]);
            float f0 = 0.f, f1 = 0.f, f2 = 0.f, f3 = 0.f;
#pragma unroll
            for (int d4 = 0; d4 < 4; d4++) {
                float4 a = h0[d4], bv = h1[d4], cv = h2[d4], dv = h3[d4];
#pragma unroll
                for (int u = 0; u < 4; u++) {
                    float wv = __ldg(w + (d4 * 4 + u) * H2);
                    f0 = fmaf((&a.x)[u], wv, f0);
                    f1 = fmaf((&bv.x)[u], wv, f1);
                    f2 = fmaf((&cv.x)[u], wv, f2);
                    f3 = fmaf((&dv.x)[u], wv, f3);
                }
            }
            mp[dpp * 256 + j]       = f0;
            mp[dpp * 256 + 64 + j]  = f1;
            mp[dpp * 256 + 128 + j] = f2;
            mp[dpp * 256 + 192 + j] = f3;
        }
        __syncthreads();
        {
            int j = tid & 63, g = tid >> 6;
            float acc = pb2[j] + mp[g * 64 + j] + mp[256 + g * 64 + j] +
                        mp[512 + g * 64 + j] + mp[768 + g * 64 + j];
            phs[g * HS + j] = prelu(acc, a2);
        }
        if (tid == 0) {
            while (((volatile int*)g_qflag)[bb] == 0) {}
            __threadfence();
        }
        __syncthreads();
        if (tid < L) qsw[tid] = __ldcg(&g_qsw[bb * L + tid]);
        __syncthreads();

        // ---- probe + p-side dot; warp reduction (2 rounds of 256 tasks) ----
#pragma unroll
        for (int r = 0; r < 2; r++) {
            int t = tid + r * 256;
            int g = t >> 7, i = t & 127;
            int v = qidx[i];
            float val = 0.f;
            if (v != PAD && (bitmap[g * 256 + (v >> 5)] >> (v & 31)) & 1u) {
                const float4* pr4 = (const float4*)(pew + (size_t)v * H2);
                const float4* ph4 = (const float4*)(&phs[g * HS]);
                float pd = 0.f;
#pragma unroll
                for (int h = 0; h < 16; h++) {
                    float4 rr = __ldg(pr4 + h), p = ph4[h];
                    pd += rr.x * p.x + rr.y * p.y + rr.z * p.z + rr.w * p.w;
                }
                val = qsw[i] * (prelu(pd, ind_a) + 1.f);
            }
#pragma unroll
            for (int off = 16; off > 0; off >>= 1)
                val += __shfl_xor_sync(0xffffffffu, val, off);
            if ((tid & 31) == 0) wpart[r][tid >> 5] = val;
        }
        __syncthreads();
        if (tid < BAGS) {
            // bag g: r = g>>1, warps (g&1)*4 .. +3
            int r = tid >> 1, w0 = (tid & 1) * 4;
            float s = wpart[r][w0] + wpart[r][w0 + 1] +
                      wpart[r][w0 + 2] + wpart[r][w0 + 3];
            __stcg(&g_ts[pair0 + tid], s);
        }

        // ---- per-b distributed epilogue: 8th block of this b finishes it ----
        if (tid == 0) {
            __threadfence();
            s_is_last = (atomicAdd(&g_bcnt[bb], 1) == 7);
        }
        __syncthreads();
        if (s_is_last) {
            if (tid < K) {
                float ts = __ldcg(&g_ts[bb * K + tid]);
                float m = ts;
#pragma unroll
                for (int off = 16; off > 0; off >>= 1)
                    m = fmaxf(m, __shfl_xor_sync(0xffffffffu, m, off));
                float tsn = (2.f * ts - m) / (m + 1e-6f);
                float dx = qloc[bb * 2]     - ploc[(bb * K + tid) * 2];
                float dy = qloc[bb * 2 + 1] - ploc[(bb * K + tid) * 2 + 1];
                float dist_sim = -logf(sqrtf(dx * dx + dy * dy) + 1.f);
                float A = *ap, Bc = *bp, C = *cp, D = *dp;
                float sig = 1.f / (1.f + expf(-(A * tsn + Bc)));
                out[bb * K + tid] = (C - sig) * (dist_sim - D);
            }
            // reset per-b state for next graph replay
            if (tid == 0) {
                g_qflag[bb] = 0;
                __threadfence();
                atomicExch(&g_bcnt[bb], 0);
            }
        }
    }
}

// ---------------------------------------------------------------------------
extern "C" void kernel_launch(void* const* d_in, const int* in_sizes, int n_in,
                              void* d_out, int out_size) {
    const int*   qbf  = (const int*)d_in[0];
    const int*   pbf  = (const int*)d_in[1];
    const float* qloc = (const float*)d_in[2];
    const float* ploc = (const float*)d_in[3];
    const float* cw   = (const float*)d_in[4];
    const float* qW1  = (const float*)d_in[5];
    const float* qb1  = (const float*)d_in[6];
    const float* qW2  = (const float*)d_in[7];
    const float* qb2  = (const float*)d_in[8];
    const float* pW1  = (const float*)d_in[9];
    const float* pb1  = (const float*)d_in[10];
    const float* pW2  = (const float*)d_in[11];
    const float* pb2  = (const float*)d_in[12];
    const float* qew  = (const float*)d_in[13];
    const float* pew  = (const float*)d_in[14];
    const float* qa0  = (const float*)d_in[15];
    const float* qa1  = (const float*)d_in[16];
    const float* qa2  = (const float*)d_in[17];
    const float* pa0  = (const float*)d_in[18];
    const float* pa1  = (const float*)d_in[19];
    const float* pa2  = (const float*)d_in[20];
    const float* inda = (const float*)d_in[21];
    const float* a    = (const float*)d_in[22];
    const float* b    = (const float*)d_in[23];
    const float* c    = (const float*)d_in[24];
    const float* d    = (const float*)d_in[25];
    float* out = (float*)d_out;

    urban_kernel<<<NBLK, NT>>>(qbf, pbf, qloc, ploc, cw,
                               qW1, qb1, qW2, qb2,
                               pW1, pb1, pW2, pb2,
                               qew, pew,
                               qa0, qa1, qa2, pa0, pa1, pa2,
                               inda, a, b, c, d, out);
}

// round 9
// speedup vs baseline: 1.0539x; 1.0539x over previous
#include <cuda_runtime.h>
#include <cuda_bf16.h>
#include <math.h>

#define PAD 8192
#define B 32
#define K 32
#define L 128
#define H1 512
#define H2 64
#define BAGS 4
#define NT 512
#define XS 516          // float stride per poi bag (2064B, 16B multiple)
#define HS 68           // multiple of 4 -> float4-safe
#define NQBLK 32
#define NPBLK 256
#define NBLK (NQBLK + NPBLK)

__device__ float g_qsw[B * L];
__device__ float g_ts[B * K];
__device__ int   g_qflag[B];
__device__ int   g_bcnt[B];

__device__ __forceinline__ float prelu(float x, float a) {
    return x >= 0.f ? x : a * x;
}

__global__ __launch_bounds__(NT, 2)
void urban_kernel(const int* __restrict__ qbf,
                  const int* __restrict__ pbf,
                  const float* __restrict__ qloc,
                  const float* __restrict__ ploc,
                  const float* __restrict__ cw,
                  const float* __restrict__ qW1, const float* __restrict__ qb1,
                  const float* __restrict__ qW2, const float* __restrict__ qb2,
                  const float* __restrict__ pW1, const float* __restrict__ pb1,
                  const float* __restrict__ pW2, const float* __restrict__ pb2,
                  const float* __restrict__ qew, const float* __restrict__ pew,
                  const float* __restrict__ qa0p, const float* __restrict__ qa1p,
                  const float* __restrict__ qa2p, const float* __restrict__ pa0p,
                  const float* __restrict__ pa1p, const float* __restrict__ pa2p,
                  const float* __restrict__ indap,
                  const float* __restrict__ ap, const float* __restrict__ bp,
                  const float* __restrict__ cp, const float* __restrict__ dp,
                  float* __restrict__ out) {
    __shared__ int      qidx[L];
    __shared__ int      pidx[BAGS * L];
    __shared__ unsigned bitmap[BAGS * 256];
    __shared__ __align__(16) float x[BAGS * XS];
    __shared__ __align__(16) float qx[H1];
    __shared__ float    mp[8 * 256];
    __shared__ float    qpart[8 * 64];
    __shared__ __align__(16) float h1s[BAGS * HS];
    __shared__ __align__(16) float phs[BAGS * HS];
    __shared__ float    qh1[H2];
    __shared__ __align__(16) float qh[H2];
    __shared__ float    qsw[L];
    __shared__ float    wpart[16];
    __shared__ int      s_is_last;

    const int tid = threadIdx.x;
    const int bid = blockIdx.x;

    if (bid < NQBLK) {
        // ================= QUERY BLOCK: one b =================
        const int b = bid;
        const float a0 = *qa0p, a1 = *qa1p, a2 = *qa2p;
        const float ind_a = *indap;

        if (tid < L) qidx[tid] = qbf[(size_t)b * L + tid];
        __syncthreads();

        // gather: one column per thread, dual accumulators, count fused
        {
            const int c = tid;
            float accA = 0.f, accB = 0.f;
            int cntA = 0, cntB = 0;
#pragma unroll 8
            for (int l = 0; l < 64; l++) {
                int v0 = qidx[l], v1 = qidx[l + 64];
                bool ok0 = (v0 != PAD), ok1 = (v1 != PAD);
                cntA += ok0; cntB += ok1;
                accA = fmaf(ok0 ? 1.f : 0.f, __ldg(cw + (size_t)v0 * H1 + c), accA);
                accB = fmaf(ok1 ? 1.f : 0.f, __ldg(cw + (size_t)v1 * H1 + c), accB);
            }
            int cnt = cntA + cntB;
            float inv = cnt > 0 ? 1.f / (float)cnt : 0.f;
            qx[c] = prelu((accA + accB) * inv, a0);
        }
        __syncthreads();

        // MLP1: thread = (j, dp), 8 d-parts of 64; float4 LDS
        {
            int j = tid & 63, dpp = tid >> 6;
            const float* w = qW1 + (size_t)(dpp * 64) * H2 + j;
            const float4* xq4 = (const float4*)(&qx[dpp * 64]);
            float acc = 0.f;
#pragma unroll 4
            for (int d4 = 0; d4 < 16; d4++) {
                float4 xv = xq4[d4];
                acc = fmaf(xv.x, __ldg(w + (d4 * 4 + 0) * H2), acc);
                acc = fmaf(xv.y, __ldg(w + (d4 * 4 + 1) * H2), acc);
                acc = fmaf(xv.z, __ldg(w + (d4 * 4 + 2) * H2), acc);
                acc = fmaf(xv.w, __ldg(w + (d4 * 4 + 3) * H2), acc);
            }
            qpart[dpp * 64 + j] = acc;
        }
        __syncthreads();
        if (tid < H2) {
            float acc = qb1[tid];
#pragma unroll
            for (int p = 0; p < 8; p++) acc += qpart[p * 64 + tid];
            qh1[tid] = prelu(acc, a1);
        }
        __syncthreads();
        if (tid < 256) {
            int j = tid & 63, dpp = tid >> 6;
            const float* w = qW2 + (size_t)(dpp * 16) * H2 + j;
            float acc = 0.f;
#pragma unroll
            for (int d = 0; d < 16; d++)
                acc = fmaf(qh1[dpp * 16 + d], __ldg(w + d * H2), acc);
            qpart[dpp * 64 + j] = acc;
        }
        __syncthreads();
        if (tid < H2) {
            float acc = qb2[tid] + qpart[tid] + qpart[64 + tid] +
                        qpart[128 + tid] + qpart[192 + tid];
            qh[tid] = prelu(acc, a2);
        }
        __syncthreads();

        if (tid < L) {
            int v = qidx[tid];
            float s = 0.f;
            if (v != PAD) {
                const float4* qr4 = (const float4*)(qew + (size_t)v * H2);
                const float4* qh4 = (const float4*)qh;
                float qd = 0.f;
#pragma unroll
                for (int h = 0; h < 16; h++) {
                    float4 r = __ldg(qr4 + h), q = qh4[h];
                    qd += r.x * q.x + r.y * q.y + r.z * q.z + r.w * q.w;
                }
                s = prelu(qd, ind_a) + 1.f;
            }
            __stcg(&g_qsw[b * L + tid], s);
        }
        __syncthreads();
        if (tid == 0) {
            __threadfence();
            atomicExch(&g_qflag[b], 1);
        }
    } else {
        // ================= POI BLOCK: 4 (b,k) pairs, same b =================
        const int pair0 = (bid - NQBLK) * BAGS;
        const int bb = pair0 >> 5;
        const float a0 = *pa0p, a1 = *pa1p, a2 = *pa2p;
        const float ind_a = *indap;

        for (int t = tid; t < BAGS * L; t += NT)
            pidx[t] = pbf[(size_t)pair0 * L + t];
        if (tid < L) qidx[tid] = qbf[(size_t)bb * L + tid];
        for (int t = tid; t < BAGS * 256; t += NT)
            bitmap[t] = 0u;
        __syncthreads();

        // ---- gather: 4 bags x 128 float4 slots, dual accumulators ----
        {
            const int g = tid >> 7, slot = tid & 127;
            const int* ip = &pidx[g * L];
            const float4* cw4 = (const float4*)cw;
            float4 aA = make_float4(0.f, 0.f, 0.f, 0.f);
            float4 aB = make_float4(0.f, 0.f, 0.f, 0.f);
            int cntA = 0, cntB = 0;
#pragma unroll 8
            for (int l = 0; l < 64; l++) {
                int v0 = ip[l], v1 = ip[l + 64];
                bool ok0 = (v0 != PAD), ok1 = (v1 != PAD);
                cntA += ok0; cntB += ok1;
                float m0 = ok0 ? 1.f : 0.f, m1 = ok1 ? 1.f : 0.f;
                float4 r0 = __ldg(cw4 + (size_t)v0 * 128 + slot);
                float4 r1 = __ldg(cw4 + (size_t)v1 * 128 + slot);
                aA.x = fmaf(m0, r0.x, aA.x); aA.y = fmaf(m0, r0.y, aA.y);
                aA.z = fmaf(m0, r0.z, aA.z); aA.w = fmaf(m0, r0.w, aA.w);
                aB.x = fmaf(m1, r1.x, aB.x); aB.y = fmaf(m1, r1.y, aB.y);
                aB.z = fmaf(m1, r1.z, aB.z); aB.w = fmaf(m1, r1.w, aB.w);
            }
            int cnt = cntA + cntB;
            float inv = cnt > 0 ? 1.f / (float)cnt : 0.f;
            float4 o;
            o.x = prelu((aA.x + aB.x) * inv, a0);
            o.y = prelu((aA.y + aB.y) * inv, a0);
            o.z = prelu((aA.z + aB.z) * inv, a0);
            o.w = prelu((aA.w + aB.w) * inv, a0);
            *(float4*)(&x[g * XS] + slot * 4) = o;
        }
        __syncthreads();

        // ---- bitmap build (same phase as MLP1) ----
        {
            int v = pidx[tid];
            if (v != PAD)
                atomicOr(&bitmap[(tid >> 7) * 256 + (v >> 5)], 1u << (v & 31));
        }
        // ---- MLP1: one W1 load feeds 4 bag-accumulators; float4 LDS ----
        {
            int j = tid & 63, dpp = tid >> 6;   // 8 d-parts of 64
            const float* w = pW1 + (size_t)(dpp * 64) * H2 + j;
            const float4* x0 = (const float4*)(&x[0 * XS + dpp * 64]);
            const float4* x1 = (const float4*)(&x[1 * XS + dpp * 64]);
            const float4* x2 = (const float4*)(&x[2 * XS + dpp * 64]);
            const float4* x3 = (const float4*)(&x[3 * XS + dpp * 64]);
            float f0 = 0.f, f1 = 0.f, f2 = 0.f, f3 = 0.f;
#pragma unroll 4
            for (int d4 = 0; d4 < 16; d4++) {
                float4 a = x0[d4], bv = x1[d4], cv = x2[d4], dv = x3[d4];
#pragma unroll
                for (int u = 0; u < 4; u++) {
                    float wv = __ldg(w + (d4 * 4 + u) * H2);
                    f0 = fmaf((&a.x)[u], wv, f0);
                    f1 = fmaf((&bv.x)[u], wv, f1);
                    f2 = fmaf((&cv.x)[u], wv, f2);
                    f3 = fmaf((&dv.x)[u], wv, f3);
                }
            }
            mp[dpp * 256 + j]       = f0;
            mp[dpp * 256 + 64 + j]  = f1;
            mp[dpp * 256 + 128 + j] = f2;
            mp[dpp * 256 + 192 + j] = f3;
        }
        __syncthreads();
        if (tid < 256) {
            int j = tid & 63, g = tid >> 6;
            float acc = pb1[j];
#pragma unroll
            for (int p = 0; p < 8; p++) acc += mp[p * 256 + g * 64 + j];
            h1s[g * HS + j] = prelu(acc, a1);
        }
        __syncthreads();
        // ---- MLP2: one W2 load feeds 4 bags; float4 LDS ----
        if (tid < 256) {
            int j = tid & 63, dpp = tid >> 6;   // 4 d-parts of 16
            const float* w = pW2 + (size_t)(dpp * 16) * H2 + j;
            const float4* h0 = (const float4*)(&h1s[0 * HS + dpp * 16]);
            const float4* h1 = (const float4*)(&h1s[1 * HS + dpp * 16]);
            const float4* h2 = (const float4*)(&h1s[2 * HS + dpp * 16]);
            const float4* h3 = (const float4*)(&h1s[3 * HS + dpp * 16]);
            float f0 = 0.f, f1 = 0.f, f2 = 0.f, f3 = 0.f;
#pragma unroll
            for (int d4 = 0; d4 < 4; d4++) {
                float4 a = h0[d4], bv = h1[d4], cv = h2[d4], dv = h3[d4];
#pragma unroll
                for (int u = 0; u < 4; u++) {
                    float wv = __ldg(w + (d4 * 4 + u) * H2);
                    f0 = fmaf((&a.x)[u], wv, f0);
                    f1 = fmaf((&bv.x)[u], wv, f1);
                    f2 = fmaf((&cv.x)[u], wv, f2);
                    f3 = fmaf((&dv.x)[u], wv, f3);
                }
            }
            mp[dpp * 256 + j]       = f0;
            mp[dpp * 256 + 64 + j]  = f1;
            mp[dpp * 256 + 128 + j] = f2;
            mp[dpp * 256 + 192 + j] = f3;
        }
        __syncthreads();
        if (tid < 256) {
            int j = tid & 63, g = tid >> 6;
            float acc = pb2[j] + mp[g * 64 + j] + mp[256 + g * 64 + j] +
                        mp[512 + g * 64 + j] + mp[768 + g * 64 + j];
            phs[g * HS + j] = prelu(acc, a2);
        }
        if (tid == 0) {
            while (((volatile int*)g_qflag)[bb] == 0) {}
            __threadfence();
        }
        __syncthreads();
        if (tid < L) qsw[tid] = __ldcg(&g_qsw[bb * L + tid]);
        __syncthreads();

        // ---- probe + p-side dot; warp-shuffle reduction ----
        {
            int g = tid >> 7, i = tid & 127;
            int v = qidx[i];
            float val = 0.f;
            if (v != PAD && (bitmap[g * 256 + (v >> 5)] >> (v & 31)) & 1u) {
                const float4* pr4 = (const float4*)(pew + (size_t)v * H2);
                const float4* ph4 = (const float4*)(&phs[g * HS]);
                float pd = 0.f;
#pragma unroll
                for (int h = 0; h < 16; h++) {
                    float4 r = __ldg(pr4 + h), p = ph4[h];
                    pd += r.x * p.x + r.y * p.y + r.z * p.z + r.w * p.w;
                }
                val = qsw[i] * (prelu(pd, ind_a) + 1.f);
            }
#pragma unroll
            for (int off = 16; off > 0; off >>= 1)
                val += __shfl_xor_sync(0xffffffffu, val, off);
            if ((tid & 31) == 0) wpart[tid >> 5] = val;
        }
        __syncthreads();
        if (tid < BAGS) {
            float s = wpart[tid * 4] + wpart[tid * 4 + 1] +
                      wpart[tid * 4 + 2] + wpart[tid * 4 + 3];
            __stcg(&g_ts[pair0 + tid], s);
        }

        // ---- per-b distributed epilogue: 8th block of this b finishes it ----
        if (tid == 0) {
            __threadfence();
            s_is_last = (atomicAdd(&g_bcnt[bb], 1) == 7);
        }
        __syncthreads();
        if (s_is_last) {
            if (tid < K) {
                float ts = __ldcg(&g_ts[bb * K + tid]);
                float m = ts;
#pragma unroll
                for (int off = 16; off > 0; off >>= 1)
                    m = fmaxf(m, __shfl_xor_sync(0xffffffffu, m, off));
                float tsn = (2.f * ts - m) / (m + 1e-6f);
                float dx = qloc[bb * 2]     - ploc[(bb * K + tid) * 2];
                float dy = qloc[bb * 2 + 1] - ploc[(bb * K + tid) * 2 + 1];
                float dist_sim = -logf(sqrtf(dx * dx + dy * dy) + 1.f);
                float A = *ap, Bc = *bp, C = *cp, D = *dp;
                float sig = 1.f / (1.f + expf(-(A * tsn + Bc)));
                out[bb * K + tid] = (C - sig) * (dist_sim - D);
            }
            if (tid == 0) {
                g_qflag[bb] = 0;
                __threadfence();
                atomicExch(&g_bcnt[bb], 0);
            }
        }
    }
}

// ---------------------------------------------------------------------------
extern "C" void kernel_launch(void* const* d_in, const int* in_sizes, int n_in,
                              void* d_out, int out_size) {
    const int*   qbf  = (const int*)d_in[0];
    const int*   pbf  = (const int*)d_in[1];
    const float* qloc = (const float*)d_in[2];
    const float* ploc = (const float*)d_in[3];
    const float* cw   = (const float*)d_in[4];
    const float* qW1  = (const float*)d_in[5];
    const float* qb1  = (const float*)d_in[6];
    const float* qW2  = (const float*)d_in[7];
    const float* qb2  = (const float*)d_in[8];
    const float* pW1  = (const float*)d_in[9];
    const float* pb1  = (const float*)d_in[10];
    const float* pW2  = (const float*)d_in[11];
    const float* pb2  = (const float*)d_in[12];
    const float* qew  = (const float*)d_in[13];
    const float* pew  = (const float*)d_in[14];
    const float* qa0  = (const float*)d_in[15];
    const float* qa1  = (const float*)d_in[16];
    const float* qa2  = (const float*)d_in[17];
    const float* pa0  = (const float*)d_in[18];
    const float* pa1  = (const float*)d_in[19];
    const float* pa2  = (const float*)d_in[20];
    const float* inda = (const float*)d_in[21];
    const float* a    = (const float*)d_in[22];
    const float* b    = (const float*)d_in[23];
    const float* c    = (const float*)d_in[24];
    const float* d    = (const float*)d_in[25];
    float* out = (float*)d_out;

    urban_kernel<<<NBLK, NT>>>(qbf, pbf, qloc, ploc, cw,
                               qW1, qb1, qW2, qb2,
                               pW1, pb1, pW2, pb2,
                               qew, pew,
                               qa0, qa1, qa2, pa0, pa1, pa2,
                               inda, a, b, c, d, out);
}

// round 10
// speedup vs baseline: 1.0760x; 1.0209x over previous
#include <cuda_runtime.h>
#include <cuda_bf16.h>
#include <math.h>

#define PAD 8192
#define B 32
#define K 32
#define L 128
#define H1 512
#define H2 64
#define BAGS 4
#define NT 512
#define XS 516          // float stride per poi bag (2064B, 16B multiple)
#define HS 68           // multiple of 4 -> float4-safe
#define NQBLK 32
#define NPBLK 256
#define NBLK (NQBLK + NPBLK)

__device__ float g_qsw[B * L];
__device__ float g_ts[B * K];
__device__ int   g_qflag[B];
__device__ int   g_bcnt[B];

__device__ __forceinline__ float prelu(float x, float a) {
    return x >= 0.f ? x : a * x;
}

__global__ __launch_bounds__(NT, 2)
void urban_kernel(const int* __restrict__ qbf,
                  const int* __restrict__ pbf,
                  const float* __restrict__ qloc,
                  const float* __restrict__ ploc,
                  const float* __restrict__ cw,
                  const float* __restrict__ qW1, const float* __restrict__ qb1,
                  const float* __restrict__ qW2, const float* __restrict__ qb2,
                  const float* __restrict__ pW1, const float* __restrict__ pb1,
                  const float* __restrict__ pW2, const float* __restrict__ pb2,
                  const float* __restrict__ qew, const float* __restrict__ pew,
                  const float* __restrict__ qa0p, const float* __restrict__ qa1p,
                  const float* __restrict__ qa2p, const float* __restrict__ pa0p,
                  const float* __restrict__ pa1p, const float* __restrict__ pa2p,
                  const float* __restrict__ indap,
                  const float* __restrict__ ap, const float* __restrict__ bp,
                  const float* __restrict__ cp, const float* __restrict__ dp,
                  float* __restrict__ out) {
    __shared__ __align__(16) int qidx[L];
    __shared__ __align__(16) int pidx[BAGS * L];
    __shared__ unsigned bitmap[BAGS * 256];
    __shared__ int      s_wcnt[16];
    __shared__ __align__(16) float x[BAGS * XS];
    __shared__ __align__(16) float qx[H1];
    __shared__ float    mp[8 * 256];
    __shared__ float    qpart[8 * 64];
    __shared__ __align__(16) float h1s[BAGS * HS];
    __shared__ __align__(16) float phs[BAGS * HS];
    __shared__ float    qh1[H2];
    __shared__ __align__(16) float qh[H2];
    __shared__ float    qsw[L];
    __shared__ float    wpart[16];
    __shared__ int      s_is_last;

    const int tid = threadIdx.x;
    const int bid = blockIdx.x;

    if (bid < NQBLK) {
        // ================= QUERY BLOCK: one b =================
        const int b = bid;
        const float a0 = *qa0p, a1 = *qa1p, a2 = *qa2p;
        const float ind_a = *indap;

        if (tid < L) {
            int v = qbf[(size_t)b * L + tid];
            qidx[tid] = v;
            unsigned bal = __ballot_sync(0xffffffffu, v != PAD);
            if ((tid & 31) == 0) s_wcnt[tid >> 5] = __popc(bal);
        }
        __syncthreads();

        // gather: one column per thread; fast unmasked path when no PAD
        {
            const int c = tid;
            const int cnt = s_wcnt[0] + s_wcnt[1] + s_wcnt[2] + s_wcnt[3];
            float accA = 0.f, accB = 0.f;
            if (cnt == L) {
#pragma unroll 4
                for (int l4 = 0; l4 < 32; l4++) {
                    int4 v = ((const int4*)qidx)[l4];
                    float r0 = __ldg(cw + (size_t)v.x * H1 + c);
                    float r1 = __ldg(cw + (size_t)v.y * H1 + c);
                    float r2 = __ldg(cw + (size_t)v.z * H1 + c);
                    float r3 = __ldg(cw + (size_t)v.w * H1 + c);
                    accA += r0 + r1;
                    accB += r2 + r3;
                }
                qx[c] = prelu((accA + accB) * (1.f / (float)L), a0);
            } else {
#pragma unroll 4
                for (int l = 0; l < L; l++) {
                    int v = qidx[l];
                    float m = (v != PAD) ? 1.f : 0.f;
                    accA = fmaf(m, __ldg(cw + (size_t)v * H1 + c), accA);
                }
                float inv = cnt > 0 ? 1.f / (float)cnt : 0.f;
                qx[c] = prelu(accA * inv, a0);
            }
        }
        __syncthreads();

        // MLP1: thread = (j, dp), 8 d-parts of 64; float4 LDS
        {
            int j = tid & 63, dpp = tid >> 6;
            const float* w = qW1 + (size_t)(dpp * 64) * H2 + j;
            const float4* xq4 = (const float4*)(&qx[dpp * 64]);
            float acc = 0.f;
#pragma unroll 4
            for (int d4 = 0; d4 < 16; d4++) {
                float4 xv = xq4[d4];
                acc = fmaf(xv.x, __ldg(w + (d4 * 4 + 0) * H2), acc);
                acc = fmaf(xv.y, __ldg(w + (d4 * 4 + 1) * H2), acc);
                acc = fmaf(xv.z, __ldg(w + (d4 * 4 + 2) * H2), acc);
                acc = fmaf(xv.w, __ldg(w + (d4 * 4 + 3) * H2), acc);
            }
            qpart[dpp * 64 + j] = acc;
        }
        __syncthreads();
        if (tid < H2) {
            float acc = qb1[tid];
#pragma unroll
            for (int p = 0; p < 8; p++) acc += qpart[p * 64 + tid];
            qh1[tid] = prelu(acc, a1);
        }
        __syncthreads();
        if (tid < 256) {
            int j = tid & 63, dpp = tid >> 6;
            const float* w = qW2 + (size_t)(dpp * 16) * H2 + j;
            float acc = 0.f;
#pragma unroll
            for (int d = 0; d < 16; d++)
                acc = fmaf(qh1[dpp * 16 + d], __ldg(w + d * H2), acc);
            qpart[dpp * 64 + j] = acc;
        }
        __syncthreads();
        if (tid < H2) {
            float acc = qb2[tid] + qpart[tid] + qpart[64 + tid] +
                        qpart[128 + tid] + qpart[192 + tid];
            qh[tid] = prelu(acc, a2);
        }
        __syncthreads();

        if (tid < L) {
            int v = qidx[tid];
            float s = 0.f;
            if (v != PAD) {
                const float4* qr4 = (const float4*)(qew + (size_t)v * H2);
                const float4* qh4 = (const float4*)qh;
                float qd = 0.f;
#pragma unroll
                for (int h = 0; h < 16; h++) {
                    float4 r = __ldg(qr4 + h), q = qh4[h];
                    qd += r.x * q.x + r.y * q.y + r.z * q.z + r.w * q.w;
                }
                s = prelu(qd, ind_a) + 1.f;
            }
            __stcg(&g_qsw[b * L + tid], s);
        }
        __syncthreads();
        if (tid == 0) {
            __threadfence();
            atomicExch(&g_qflag[b], 1);
        }
    } else {
        // ================= POI BLOCK: 4 (b,k) pairs, same b =================
        const int pair0 = (bid - NQBLK) * BAGS;
        const int bb = pair0 >> 5;
        const float a0 = *pa0p, a1 = *pa1p, a2 = *pa2p;
        const float ind_a = *indap;

        {
            int v = pbf[(size_t)pair0 * L + tid];
            pidx[tid] = v;
            unsigned bal = __ballot_sync(0xffffffffu, v != PAD);
            if ((tid & 31) == 0) s_wcnt[tid >> 5] = __popc(bal);
        }
        if (tid < L) qidx[tid] = qbf[(size_t)bb * L + tid];
        {
            bitmap[tid] = 0u;
            bitmap[tid + 512] = 0u;
        }
        __syncthreads();

        // ---- gather: 4 bags x 128 float4 slots; fast unmasked path ----
        {
            const int g = tid >> 7, slot = tid & 127;
            const int* ip = &pidx[g * L];
            const float4* cw4 = (const float4*)cw;
            float4 aA = make_float4(0.f, 0.f, 0.f, 0.f);
            float4 aB = make_float4(0.f, 0.f, 0.f, 0.f);
            const int cnt = s_wcnt[g * 4] + s_wcnt[g * 4 + 1] +
                            s_wcnt[g * 4 + 2] + s_wcnt[g * 4 + 3];
            if (cnt == L) {
#pragma unroll 4
                for (int l4 = 0; l4 < 32; l4++) {
                    int4 v = ((const int4*)ip)[l4];
                    float4 r0 = __ldg(cw4 + (size_t)v.x * 128 + slot);
                    float4 r1 = __ldg(cw4 + (size_t)v.y * 128 + slot);
                    float4 r2 = __ldg(cw4 + (size_t)v.z * 128 + slot);
                    float4 r3 = __ldg(cw4 + (size_t)v.w * 128 + slot);
                    aA.x += r0.x + r1.x; aA.y += r0.y + r1.y;
                    aA.z += r0.z + r1.z; aA.w += r0.w + r1.w;
                    aB.x += r2.x + r3.x; aB.y += r2.y + r3.y;
                    aB.z += r2.z + r3.z; aB.w += r2.w + r3.w;
                }
                const float inv = 1.f / (float)L;
                float4 o;
                o.x = prelu((aA.x + aB.x) * inv, a0);
                o.y = prelu((aA.y + aB.y) * inv, a0);
                o.z = prelu((aA.z + aB.z) * inv, a0);
                o.w = prelu((aA.w + aB.w) * inv, a0);
                *(float4*)(&x[g * XS] + slot * 4) = o;
            } else {
#pragma unroll 4
                for (int l = 0; l < L; l++) {
                    int v = ip[l];
                    float m = (v != PAD) ? 1.f : 0.f;
                    float4 r = __ldg(cw4 + (size_t)v * 128 + slot);
                    aA.x = fmaf(m, r.x, aA.x); aA.y = fmaf(m, r.y, aA.y);
                    aA.z = fmaf(m, r.z, aA.z); aA.w = fmaf(m, r.w, aA.w);
                }
                float inv = cnt > 0 ? 1.f / (float)cnt : 0.f;
                float4 o;
                o.x = prelu(aA.x * inv, a0); o.y = prelu(aA.y * inv, a0);
                o.z = prelu(aA.z * inv, a0); o.w = prelu(aA.w * inv, a0);
                *(float4*)(&x[g * XS] + slot * 4) = o;
            }
        }
        __syncthreads();

        // ---- bitmap build (same phase as MLP1) ----
        {
            int v = pidx[tid];
            if (v != PAD)
                atomicOr(&bitmap[(tid >> 7) * 256 + (v >> 5)], 1u << (v & 31));
        }
        // ---- MLP1: one W1 load feeds 4 bag-accumulators; float4 LDS ----
        {
            int j = tid & 63, dpp = tid >> 6;   // 8 d-parts of 64
            const float* w = pW1 + (size_t)(dpp * 64) * H2 + j;
            const float4* x0 = (const float4*)(&x[0 * XS + dpp * 64]);
            const float4* x1 = (const float4*)(&x[1 * XS + dpp * 64]);
            const float4* x2 = (const float4*)(&x[2 * XS + dpp * 64]);
            const float4* x3 = (const float4*)(&x[3 * XS + dpp * 64]);
            float f0 = 0.f, f1 = 0.f, f2 = 0.f, f3 = 0.f;
#pragma unroll 4
            for (int d4 = 0; d4 < 16; d4++) {
                float4 a = x0[d4], bv = x1[d4], cv = x2[d4], dv = x3[d4];
#pragma unroll
                for (int u = 0; u < 4; u++) {
                    float wv = __ldg(w + (d4 * 4 + u) * H2);
                    f0 = fmaf((&a.x)[u], wv, f0);
                    f1 = fmaf((&bv.x)[u], wv, f1);
                    f2 = fmaf((&cv.x)[u], wv, f2);
                    f3 = fmaf((&dv.x)[u], wv, f3);
                }
            }
            mp[dpp * 256 + j]       = f0;
            mp[dpp * 256 + 64 + j]  = f1;
            mp[dpp * 256 + 128 + j] = f2;
            mp[dpp * 256 + 192 + j] = f3;
        }
        __syncthreads();
        if (tid < 256) {
            int j = tid & 63, g = tid >> 6;
            float acc = pb1[j];
#pragma unroll
            for (int p = 0; p < 8; p++) acc += mp[p * 256 + g * 64 + j];
            h1s[g * HS + j] = prelu(acc, a1);
        }
        __syncthreads();
        // ---- MLP2: one W2 load feeds 4 bags; float4 LDS ----
        if (tid < 256) {
            int j = tid & 63, dpp = tid >> 6;   // 4 d-parts of 16
            const float* w = pW2 + (size_t)(dpp * 16) * H2 + j;
            const float4* h0 = (const float4*)(&h1s[0 * HS + dpp * 16]);
            const float4* h1 = (const float4*)(&h1s[1 * HS + dpp * 16]);
            const float4* h2 = (const float4*)(&h1s[2 * HS + dpp * 16]);
            const float4* h3 = (const float4*)(&h1s[3 * HS + dpp * 16]);
            float f0 = 0.f, f1 = 0.f, f2 = 0.f, f3 = 0.f;
#pragma unroll
            for (int d4 = 0; d4 < 4; d4++) {
                float4 a = h0[d4], bv = h1[d4], cv = h2[d4], dv = h3[d4];
#pragma unroll
                for (int u = 0; u < 4; u++) {
                    float wv = __ldg(w + (d4 * 4 + u) * H2);
                    f0 = fmaf((&a.x)[u], wv, f0);
                    f1 = fmaf((&bv.x)[u], wv, f1);
                    f2 = fmaf((&cv.x)[u], wv, f2);
                    f3 = fmaf((&dv.x)[u], wv, f3);
                }
            }
            mp[dpp * 256 + j]       = f0;
            mp[dpp * 256 + 64 + j]  = f1;
            mp[dpp * 256 + 128 + j] = f2;
            mp[dpp * 256 + 192 + j] = f3;
        }
        __syncthreads();
        if (tid < 256) {
            int j = tid & 63, g = tid >> 6;
            float acc = pb2[j] + mp[g * 64 + j] + mp[256 + g * 64 + j] +
                        mp[512 + g * 64 + j] + mp[768 + g * 64 + j];
            phs[g * HS + j] = prelu(acc, a2);
        }
        if (tid == 0) {
            while (((volatile int*)g_qflag)[bb] == 0) {}
            __threadfence();
        }
        __syncthreads();
        if (tid < L) qsw[tid] = __ldcg(&g_qsw[bb * L + tid]);
        __syncthreads();

        // ---- probe + p-side dot; warp-shuffle reduction ----
        {
            int g = tid >> 7, i = tid & 127;
            int v = qidx[i];
            float val = 0.f;
            if (v != PAD && (bitmap[g * 256 + (v >> 5)] >> (v & 31)) & 1u) {
                const float4* pr4 = (const float4*)(pew + (size_t)v * H2);
                const float4* ph4 = (const float4*)(&phs[g * HS]);
                float pd = 0.f;
#pragma unroll
                for (int h = 0; h < 16; h++) {
                    float4 r = __ldg(pr4 + h), p = ph4[h];
                    pd += r.x * p.x + r.y * p.y + r.z * p.z + r.w * p.w;
                }
                val = qsw[i] * (prelu(pd, ind_a) + 1.f);
            }
#pragma unroll
            for (int off = 16; off > 0; off >>= 1)
                val += __shfl_xor_sync(0xffffffffu, val, off);
            if ((tid & 31) == 0) wpart[tid >> 5] = val;
        }
        __syncthreads();
        if (tid < BAGS) {
            float s = wpart[tid * 4] + wpart[tid * 4 + 1] +
                      wpart[tid * 4 + 2] + wpart[tid * 4 + 3];
            __stcg(&g_ts[pair0 + tid], s);
        }

        // ---- per-b distributed epilogue: 8th block of this b finishes it ----
        if (tid == 0) {
            __threadfence();
            s_is_last = (atomicAdd(&g_bcnt[bb], 1) == 7);
        }
        __syncthreads();
        if (s_is_last) {
            if (tid < K) {
                float ts = __ldcg(&g_ts[bb * K + tid]);
                float m = ts;
#pragma unroll
                for (int off = 16; off > 0; off >>= 1)
                    m = fmaxf(m, __shfl_xor_sync(0xffffffffu, m, off));
                float tsn = (2.f * ts - m) / (m + 1e-6f);
                float dx = qloc[bb * 2]     - ploc[(bb * K + tid) * 2];
                float dy = qloc[bb * 2 + 1] - ploc[(bb * K + tid) * 2 + 1];
                float dist_sim = -logf(sqrtf(dx * dx + dy * dy) + 1.f);
                float A = *ap, Bc = *bp, C = *cp, D = *dp;
                float sig = 1.f / (1.f + expf(-(A * tsn + Bc)));
                out[bb * K + tid] = (C - sig) * (dist_sim - D);
            }
            if (tid == 0) {
                g_qflag[bb] = 0;
                __threadfence();
                atomicExch(&g_bcnt[bb], 0);
            }
        }
    }
}

// ---------------------------------------------------------------------------
extern "C" void kernel_launch(void* const* d_in, const int* in_sizes, int n_in,
                              void* d_out, int out_size) {
    const int*   qbf  = (const int*)d_in[0];
    const int*   pbf  = (const int*)d_in[1];
    const float* qloc = (const float*)d_in[2];
    const float* ploc = (const float*)d_in[3];
    const float* cw   = (const float*)d_in[4];
    const float* qW1  = (const float*)d_in[5];
    const float* qb1  = (const float*)d_in[6];
    const float* qW2  = (const float*)d_in[7];
    const float* qb2  = (const float*)d_in[8];
    const float* pW1  = (const float*)d_in[9];
    const float* pb1  = (const float*)d_in[10];
    const float* pW2  = (const float*)d_in[11];
    const float* pb2  = (const float*)d_in[12];
    const float* qew  = (const float*)d_in[13];
    const float* pew  = (const float*)d_in[14];
    const float* qa0  = (const float*)d_in[15];
    const float* qa1  = (const float*)d_in[16];
    const float* qa2  = (const float*)d_in[17];
    const float* pa0  = (const float*)d_in[18];
    const float* pa1  = (const float*)d_in[19];
    const float* pa2  = (const float*)d_in[20];
    const float* inda = (const float*)d_in[21];
    const float* a    = (const float*)d_in[22];
    const float* b    = (const float*)d_in[23];
    const float* c    = (const float*)d_in[24];
    const float* d    = (const float*)d_in[25];
    float* out = (float*)d_out;

    urban_kernel<<<NBLK, NT>>>(qbf, pbf, qloc, ploc, cw,
                               qW1, qb1, qW2, qb2,
                               pW1, pb1, pW2, pb2,
                               qew, pew,
                               qa0, qa1, qa2, pa0, pa1, pa2,
                               inda, a, b, c, d, out);
}